// round 2
// baseline (speedup 1.0000x reference)
#include <cuda_runtime.h>
#include <math.h>

#define W 512
#define H 512
#define HW (H * W)
#define TWO_PI 6.283185307179586f
#define ALPHA_THRESH (1.0f / 255.0f)

#define NMAX 5000
#define TILES_X 32
#define TILES_Y 32
#define NTILES (TILES_X * TILES_Y)
#define CAP 1024          // max gaussians per tile (worst case well under this)

// Packed per-gaussian params: q0 = (cx, cy, A, B), q1 = (C, op, col0, col1), q2.x = col2
__device__ float4 g_params[NMAX * 3];
__device__ int    g_tilecount[NTILES];          // zero-init BSS; render kernel re-zeroes
__device__ int    g_tilelist[NTILES * CAP];

__global__ void bin_kernel(const float* __restrict__ xyz,
                           const float* __restrict__ scaling,
                           const float* __restrict__ rot,
                           const float* __restrict__ feat,
                           const float* __restrict__ opac,
                           int n) {
    int g = blockIdx.x * blockDim.x + threadIdx.x;
    if (g >= n) return;

    float mx = tanhf(xyz[2 * g]);
    float my = tanhf(xyz[2 * g + 1]);
    float sx = fabsf(scaling[2 * g] + 0.5f);
    float sy = fabsf(scaling[2 * g + 1] + 0.5f);
    float theta = (1.0f / (1.0f + expf(-rot[g]))) * TWO_PI;

    float cx = 0.5f * ((mx + 1.0f) * (float)W - 1.0f);
    float cy = 0.5f * ((my + 1.0f) * (float)H - 1.0f);

    float sth, cth;
    sincosf(theta, &sth, &cth);
    float sx2 = sx * sx;
    float sy2 = sy * sy;
    float a = cth * cth * sx2 + sth * sth * sy2;
    float b = cth * sth * (sx2 - sy2);
    float c = sth * sth * sx2 + cth * cth * sy2;
    float det = a * c - b * b;
    if (!(det > 0.0f)) return;
    float inv_det = 1.0f / fmaxf(det, 1e-12f);
    float A = c * inv_det;
    float B = -b * inv_det;
    float C = a * inv_det;

    float op = opac[g];
    float tmax = logf(op * 255.0f);     // alpha > 1/255 <=> sigma < tmax
    if (!(tmax > 0.0f)) return;

    float rx = sqrtf(2.0f * tmax * a) + 1.0f;   // +1 margin; exact test in render
    float ry = sqrtf(2.0f * tmax * c) + 1.0f;

    int x0 = max(0, (int)ceilf(cx - rx));
    int x1 = min(W - 1, (int)floorf(cx + rx));
    int y0 = max(0, (int)ceilf(cy - ry));
    int y1 = min(H - 1, (int)floorf(cy + ry));
    if (x1 < x0 || y1 < y0) return;

    g_params[g * 3 + 0] = make_float4(cx, cy, A, B);
    g_params[g * 3 + 1] = make_float4(C, op, feat[3 * g], feat[3 * g + 1]);
    g_params[g * 3 + 2] = make_float4(feat[3 * g + 2], 0.0f, 0.0f, 0.0f);

    int tx0 = x0 >> 4, tx1 = x1 >> 4;
    int ty0 = y0 >> 4, ty1 = y1 >> 4;
    for (int ty = ty0; ty <= ty1; ty++) {
        for (int tx = tx0; tx <= tx1; tx++) {
            int t = ty * TILES_X + tx;
            int s = atomicAdd(&g_tilecount[t], 1);
            if (s < CAP) g_tilelist[t * CAP + s] = g;
        }
    }
}

#define CHUNK 128

__global__ void render_kernel(float* __restrict__ out) {
    __shared__ float4 sp[CHUNK * 3];

    int tile = blockIdx.x;
    int tx = tile & (TILES_X - 1);
    int ty = tile >> 5;
    int lx = threadIdx.x & 15;
    int ly = threadIdx.x >> 4;
    int px = tx * 16 + lx;
    int py = ty * 16 + ly;
    float fx = (float)px;
    float fy = (float)py;

    int cnt = min(g_tilecount[tile], CAP);

    float acc0 = 0.0f, acc1 = 0.0f, acc2 = 0.0f;

    for (int base = 0; base < cnt; base += CHUNK) {
        int m = min(CHUNK, cnt - base);
        __syncthreads();
        for (int i = threadIdx.x; i < m * 3; i += 256) {
            int e = i / 3;
            int q = i - e * 3;
            int gidx = g_tilelist[tile * CAP + base + e];
            sp[e * 3 + q] = g_params[gidx * 3 + q];
        }
        __syncthreads();

        for (int e = 0; e < m; e++) {
            float4 q0 = sp[e * 3 + 0];   // cx, cy, A, B
            float4 q1 = sp[e * 3 + 1];   // C, op, c0, c1
            float  c2 = sp[e * 3 + 2].x;
            float dx = q0.x - fx;
            float dy = q0.y - fy;
            float sigma = 0.5f * (q0.z * dx * dx + q1.x * dy * dy) + q0.w * dx * dy;
            float alpha = q1.y * __expf(-sigma);
            if (sigma >= 0.0f && alpha > ALPHA_THRESH) {
                acc0 += alpha * q1.z;
                acc1 += alpha * q1.w;
                acc2 += alpha * c2;
            }
        }
    }

    int pix = py * W + px;
    out[pix]          = fminf(fmaxf(acc0, 0.0f), 1.0f);
    out[HW + pix]     = fminf(fmaxf(acc1, 0.0f), 1.0f);
    out[2 * HW + pix] = fminf(fmaxf(acc2, 0.0f), 1.0f);

    // leave counters zeroed for the next graph replay
    __syncthreads();
    if (threadIdx.x == 0) g_tilecount[tile] = 0;
}

extern "C" void kernel_launch(void* const* d_in, const int* in_sizes, int n_in,
                              void* d_out, int out_size) {
    const float* xyz     = (const float*)d_in[0];  // (N,2)
    const float* scaling = (const float*)d_in[1];  // (N,2)
    const float* rot     = (const float*)d_in[2];  // (N,1)
    const float* feat    = (const float*)d_in[3];  // (N,3)
    const float* opac    = (const float*)d_in[4];  // (N,1)
    float* out = (float*)d_out;                     // (1,3,512,512)

    int n = in_sizes[0] / 2;

    bin_kernel<<<(n + 255) / 256, 256>>>(xyz, scaling, rot, feat, opac, n);
    render_kernel<<<NTILES, 256>>>(out);
}